// round 3
// baseline (speedup 1.0000x reference)
#include <cuda_runtime.h>
#include <cuda_bf16.h>
#include <math.h>

// Shapes (fixed by the benchmark)
#define BB 2
#define SS 8192
#define DD 64
#define D2 128           // 2*D
#define MT 64            // query rows per CTA tile
#define NT 64            // keys per kv step
#define NQT (SS / MT)    // 128 q-tiles per batch

// Smem strides (floats)
#define QT_STR 68
#define KT_STR 68
#define V_STR  136
#define P_STR  68
#define SM_QT_OFF 0
#define SM_KT_OFF (128 * QT_STR)                 // 8704
#define SM_V_OFF  (SM_KT_OFF + 128 * KT_STR)     // 17408
#define SM_P_OFF  (SM_V_OFF + 64 * V_STR)        // 26112
#define SM_FLOATS (SM_P_OFF + 64 * P_STR)        // 30464
#define SM_BYTES  (SM_FLOATS * 4)                // 121856

// Scratch (static device globals -- no allocation allowed)
__device__ float g_Q[BB * SS * D2];   // 8 MB
__device__ float g_K[BB * SS * D2];   // 8 MB
__device__ float g_R[BB * SS * D2];   // 8 MB  (retrieved)

// -------------------- Kernel 1: prep Q (LUT cos) and K --------------------
// Bit-match reference fp32 chain: no FMA contraction, IEEE div.
__global__ void prep_kernel(const float* __restrict__ sr,
                            const float* __restrict__ si,
                            const float* __restrict__ pos,
                            const float* __restrict__ w_q,
                            const float* __restrict__ b_q) {
    const float PHI_F     = (float)1.6180339887498948482;
    const float INV2PI    = (float)(1.0 / 6.283185307179586476925286766559);
    const float LUTN_F    = 4096.0f;
    const float ANG_STEP  = (float)(6.283185307179586476925286766559 / 4096.0);

    int idx = blockIdx.x * blockDim.x + threadIdx.x;   // over B*S*D
    if (idx >= BB * SS * DD) return;
    int d = idx & (DD - 1);
    int s = (idx >> 6) & (SS - 1);
    int b = idx >> 19;

    float wl   = 1.0f + fabsf(w_q[d]);
    float bq   = b_q[d];
    float tphi = __fmul_rn(pos[s], PHI_F);

    float xr = sr[idx];
    float xi = si[idx];

    // theta = (x / wl + b) + t_phi  (all separately rounded)
    float thr = __fadd_rn(__fadd_rn(__fdiv_rn(xr, wl), bq), tphi);
    float thi = __fadd_rn(__fadd_rn(__fdiv_rn(xi, wl), bq), tphi);

    // LUT cos: frac = theta/2pi - floor(.); idx = clip(floor(frac*4096),0,4095)
    float fr = __fmul_rn(thr, INV2PI);
    fr = __fsub_rn(fr, floorf(fr));
    int ir = (int)floorf(__fmul_rn(fr, LUTN_F));
    ir = ir < 0 ? 0 : (ir > 4095 ? 4095 : ir);
    float cr = cosf(__fmul_rn((float)ir, ANG_STEP));

    float fi = __fmul_rn(thi, INV2PI);
    fi = __fsub_rn(fi, floorf(fi));
    int ii = (int)floorf(__fmul_rn(fi, LUTN_F));
    ii = ii < 0 ? 0 : (ii > 4095 ? 4095 : ii);
    float ci = cosf(__fmul_rn((float)ii, ANG_STEP));

    int base = (b * SS + s) * D2;
    g_Q[base + d]      = cr;
    g_Q[base + d + DD] = ci;
    g_K[base + d]      = xr;
    g_K[base + d + DD] = xi;
}

// -------------------- Kernel 2: causal flash attention (fp32) --------------------
// No-running-max softmax: logits are bounded (|score| <= ~20), so raw exp
// accumulation in fp32 is safe; normalize by row sum at the end.
__global__ __launch_bounds__(256, 1) void attn_kernel() {
    extern __shared__ float sm[];
    float* sQT = sm + SM_QT_OFF;   // [128][68]  Q^T (d-major)
    float* sKT = sm + SM_KT_OFF;   // [128][68]  K^T (d-major)
    float* sV  = sm + SM_V_OFF;    // [64][136]  K row-major (acts as V)
    float* sP  = sm + SM_P_OFF;    // [64][68]   P[row][key]

    const int bid = blockIdx.x;
    const int b   = bid & 1;
    const int qt  = (NQT - 1) - (bid >> 1);  // longest tiles scheduled first
    const int q0  = qt << 6;

    const float* __restrict__ Qg = g_Q + b * (SS * D2);
    const float* __restrict__ Kg = g_K + b * (SS * D2);

    const int tid = threadIdx.x;
    const int tr  = tid >> 4;     // 0..15 (row group)
    const int tc  = tid & 15;     // 0..15 (col group)
    const int r0  = tr << 2;      // 4 rows
    const int c0  = tc << 2;      // 4 score cols
    const int d0  = tc << 3;      // 8 output d cols

    // Load Q tile transposed
    for (int e = tid; e < MT * D2; e += 256) {
        int r = e >> 7, d = e & 127;
        sQT[d * QT_STR + r] = Qg[(q0 + r) * D2 + d];
    }

    float acc[4][8];
    #pragma unroll
    for (int i = 0; i < 4; i++)
        #pragma unroll
        for (int x = 0; x < 8; x++) acc[i][x] = 0.f;
    float lsum[4] = {0.f, 0.f, 0.f, 0.f};

    const float SC = 0.0883883476483184405501f;  // 1/sqrt(128)
    const int nkt = qt + 1;

    for (int j = 0; j < nkt; ++j) {
        const int k0 = j << 6;
        __syncthreads();  // previous iter's smem reads done
        for (int e = tid; e < NT * D2; e += 256) {
            int r = e >> 7, d = e & 127;
            float v = Kg[(k0 + r) * D2 + d];
            sKT[d * KT_STR + r] = v;
            sV[r * V_STR + d]   = v;
        }
        __syncthreads();

        // ---- scores: S = Q K^T (64x64, contraction over d=128) ----
        float s00=0,s01=0,s02=0,s03=0, s10=0,s11=0,s12=0,s13=0;
        float s20=0,s21=0,s22=0,s23=0, s30=0,s31=0,s32=0,s33=0;
        #pragma unroll 8
        for (int k = 0; k < 128; ++k) {
            const float4 qv = *reinterpret_cast<const float4*>(sQT + k * QT_STR + r0);
            const float4 kv = *reinterpret_cast<const float4*>(sKT + k * KT_STR + c0);
            s00 += qv.x * kv.x; s01 += qv.x * kv.y; s02 += qv.x * kv.z; s03 += qv.x * kv.w;
            s10 += qv.y * kv.x; s11 += qv.y * kv.y; s12 += qv.y * kv.z; s13 += qv.y * kv.w;
            s20 += qv.z * kv.x; s21 += qv.z * kv.y; s22 += qv.z * kv.z; s23 += qv.z * kv.w;
            s30 += qv.w * kv.x; s31 += qv.w * kv.y; s32 += qv.w * kv.z; s33 += qv.w * kv.w;
        }

        // ---- mask + exp + write P ----
        float sarr[4][4] = {{s00,s01,s02,s03},{s10,s11,s12,s13},
                            {s20,s21,s22,s23},{s30,s31,s32,s33}};
        #pragma unroll
        for (int i = 0; i < 4; i++) {
            const int gq = q0 + r0 + i;
            #pragma unroll
            for (int jj = 0; jj < 4; jj++) {
                const int gk = k0 + c0 + jj;
                float p = (gk <= gq) ? __expf(sarr[i][jj] * SC) : 0.f;
                lsum[i] += p;
                sP[(r0 + i) * P_STR + (c0 + jj)] = p;
            }
        }
        __syncthreads();

        // ---- PV: acc += P * V (64x128, contraction over 64 keys) ----
        #pragma unroll 4
        for (int k = 0; k < 64; ++k) {
            const float p0 = sP[(r0 + 0) * P_STR + k];
            const float p1 = sP[(r0 + 1) * P_STR + k];
            const float p2 = sP[(r0 + 2) * P_STR + k];
            const float p3 = sP[(r0 + 3) * P_STR + k];
            const float4 v0 = *reinterpret_cast<const float4*>(sV + k * V_STR + d0);
            const float4 v1 = *reinterpret_cast<const float4*>(sV + k * V_STR + d0 + 4);
            acc[0][0] += p0*v0.x; acc[0][1] += p0*v0.y; acc[0][2] += p0*v0.z; acc[0][3] += p0*v0.w;
            acc[0][4] += p0*v1.x; acc[0][5] += p0*v1.y; acc[0][6] += p0*v1.z; acc[0][7] += p0*v1.w;
            acc[1][0] += p1*v0.x; acc[1][1] += p1*v0.y; acc[1][2] += p1*v0.z; acc[1][3] += p1*v0.w;
            acc[1][4] += p1*v1.x; acc[1][5] += p1*v1.y; acc[1][6] += p1*v1.z; acc[1][7] += p1*v1.w;
            acc[2][0] += p2*v0.x; acc[2][1] += p2*v0.y; acc[2][2] += p2*v0.z; acc[2][3] += p2*v0.w;
            acc[2][4] += p2*v1.x; acc[2][5] += p2*v1.y; acc[2][6] += p2*v1.z; acc[2][7] += p2*v1.w;
            acc[3][0] += p3*v0.x; acc[3][1] += p3*v0.y; acc[3][2] += p3*v0.z; acc[3][3] += p3*v0.w;
            acc[3][4] += p3*v1.x; acc[3][5] += p3*v1.y; acc[3][6] += p3*v1.z; acc[3][7] += p3*v1.w;
        }
    }

    // Row-sum reduction across the 16 col-threads (within 16-lane groups)
    #pragma unroll
    for (int off = 1; off < 16; off <<= 1) {
        #pragma unroll
        for (int i = 0; i < 4; i++)
            lsum[i] += __shfl_xor_sync(0xffffffffu, lsum[i], off);
    }

    float* __restrict__ Rg = g_R + b * (SS * D2);
    #pragma unroll
    for (int i = 0; i < 4; i++) {
        const float inv = 1.0f / lsum[i];
        const int row = q0 + r0 + i;
        float4 o0, o1;
        o0.x = acc[i][0]*inv; o0.y = acc[i][1]*inv; o0.z = acc[i][2]*inv; o0.w = acc[i][3]*inv;
        o1.x = acc[i][4]*inv; o1.y = acc[i][5]*inv; o1.z = acc[i][6]*inv; o1.w = acc[i][7]*inv;
        *reinterpret_cast<float4*>(Rg + row * D2 + d0)     = o0;
        *reinterpret_cast<float4*>(Rg + row * D2 + d0 + 4) = o1;
    }
}

// -------------------- Kernel 3: EMA scan + fold --------------------
__global__ void ema_kernel(const float* __restrict__ alpha_p,
                           float* __restrict__ out) {
    const int tid = threadIdx.x;   // 0..127
    const int b = tid >> 6;
    const int d = tid & 63;
    const float alpha = alpha_p[0];
    const float a  = 1.0f / (1.0f + expf(-alpha));
    const float na = 1.0f - a;

    const float* __restrict__ R = g_R + b * (SS * D2);
    float e1 = 0.f, e2 = 0.f;
    #pragma unroll 4
    for (int t = 0; t < SS; ++t) {
        const float r1 = R[t * D2 + d];
        const float r2 = R[t * D2 + d + DD];
        e1 = a * r1 + na * e1;
        e2 = a * r2 + na * e2;
        out[(b * SS + t) * DD + d] = e1 + e2;
    }
}

// -------------------- launch --------------------
extern "C" void kernel_launch(void* const* d_in, const int* in_sizes, int n_in,
                              void* d_out, int out_size) {
    const float* sr    = (const float*)d_in[0];
    const float* si    = (const float*)d_in[1];
    const float* pos   = (const float*)d_in[2];
    const float* w_q   = (const float*)d_in[3];
    const float* b_q   = (const float*)d_in[4];
    const float* alpha = (const float*)d_in[5];
    float* out = (float*)d_out;

    (void)in_sizes; (void)n_in; (void)out_size;

    cudaFuncSetAttribute(attn_kernel,
                         cudaFuncAttributeMaxDynamicSharedMemorySize, SM_BYTES);

    const int nprep = BB * SS * DD;
    prep_kernel<<<(nprep + 255) / 256, 256>>>(sr, si, pos, w_q, b_q);
    attn_kernel<<<BB * NQT, 256, SM_BYTES>>>();
    ema_kernel<<<1, 128>>>(alpha, out);
}

// round 5
// speedup vs baseline: 2.1948x; 2.1948x over previous
#include <cuda_runtime.h>
#include <cuda_bf16.h>
#include <math.h>
#include <stdint.h>

// Shapes (fixed by the benchmark)
#define BB 2
#define SS 8192
#define DD 64
#define D2 128           // 2*D

// Smem layout: 4 bf16 tiles, 256B rows, XOR-swizzled in 16B units
#define OFF_QH 0          // 128 x 128 bf16 = 32KB
#define OFF_QL 32768
#define OFF_KH 65536      // 64 x 128 bf16 = 16KB
#define OFF_KL 81920
#define SM_BYTES 98304

// Scratch (static device globals -- no allocation allowed)
__device__ __nv_bfloat16 g_Qh[BB * SS * D2];
__device__ __nv_bfloat16 g_Ql[BB * SS * D2];
__device__ __nv_bfloat16 g_Kh[BB * SS * D2];
__device__ __nv_bfloat16 g_Kl[BB * SS * D2];
__device__ float g_O[2][BB * SS * D2];   // unnormalized O per kv-split (16MB)
__device__ float g_Ls[2][BB * SS];       // row exp-sums per split
__device__ float g_Z[BB * SS * DD];      // combined + folded retrieved

// ---------------- helpers ----------------
__device__ __forceinline__ uint32_t smem_u32(const void* p) {
    uint32_t a;
    asm("{ .reg .u64 t; cvta.to.shared.u64 t, %1; cvt.u32.u64 %0, t; }"
        : "=r"(a) : "l"(p));
    return a;
}
__device__ __forceinline__ void ldsm4(uint32_t* r, uint32_t addr) {
    asm volatile("ldmatrix.sync.aligned.m8n8.x4.shared.b16 {%0,%1,%2,%3}, [%4];"
        : "=r"(r[0]), "=r"(r[1]), "=r"(r[2]), "=r"(r[3]) : "r"(addr));
}
__device__ __forceinline__ void ldsm4t(uint32_t* r, uint32_t addr) {
    asm volatile("ldmatrix.sync.aligned.m8n8.x4.trans.shared.b16 {%0,%1,%2,%3}, [%4];"
        : "=r"(r[0]), "=r"(r[1]), "=r"(r[2]), "=r"(r[3]) : "r"(addr));
}
__device__ __forceinline__ void mma16816(float* c, const uint32_t* a, const uint32_t* b) {
    asm volatile(
        "mma.sync.aligned.m16n8k16.row.col.f32.bf16.bf16.f32 "
        "{%0,%1,%2,%3}, {%4,%5,%6,%7}, {%8,%9}, {%0,%1,%2,%3};"
        : "+f"(c[0]), "+f"(c[1]), "+f"(c[2]), "+f"(c[3])
        : "r"(a[0]), "r"(a[1]), "r"(a[2]), "r"(a[3]), "r"(b[0]), "r"(b[1]));
}
// pack (x -> lo, y -> hi) as bf16x2, plus residual pack
__device__ __forceinline__ void split2(float x, float y, uint32_t& h, uint32_t& l) {
    asm("cvt.rn.bf16x2.f32 %0, %1, %2;" : "=r"(h) : "f"(y), "f"(x));
    float hx = __uint_as_float(h << 16);
    float hy = __uint_as_float(h & 0xffff0000u);
    asm("cvt.rn.bf16x2.f32 %0, %1, %2;" : "=r"(l) : "f"(y - hy), "f"(x - hx));
}

// -------------------- Kernel 1: prep Q (LUT cos) and K, bf16 hi/lo --------------------
__global__ void prep_kernel(const float* __restrict__ sr,
                            const float* __restrict__ si,
                            const float* __restrict__ pos,
                            const float* __restrict__ w_q,
                            const float* __restrict__ b_q) {
    const float PHI_F     = (float)1.6180339887498948482;
    const float INV2PI    = (float)(1.0 / 6.283185307179586476925286766559);
    const float LUTN_F    = 4096.0f;
    const float ANG_STEP  = (float)(6.283185307179586476925286766559 / 4096.0);

    int idx = blockIdx.x * blockDim.x + threadIdx.x;   // over B*S*D
    if (idx >= BB * SS * DD) return;
    int d = idx & (DD - 1);
    int s = (idx >> 6) & (SS - 1);
    int b = idx >> 19;

    float wl   = 1.0f + fabsf(w_q[d]);
    float bq   = b_q[d];
    float tphi = __fmul_rn(pos[s], PHI_F);

    float xr = sr[idx];
    float xi = si[idx];

    float thr = __fadd_rn(__fadd_rn(__fdiv_rn(xr, wl), bq), tphi);
    float thi = __fadd_rn(__fadd_rn(__fdiv_rn(xi, wl), bq), tphi);

    float fr = __fmul_rn(thr, INV2PI);
    fr = __fsub_rn(fr, floorf(fr));
    int ir = (int)floorf(__fmul_rn(fr, LUTN_F));
    ir = ir < 0 ? 0 : (ir > 4095 ? 4095 : ir);
    float cr = cosf(__fmul_rn((float)ir, ANG_STEP));

    float fi = __fmul_rn(thi, INV2PI);
    fi = __fsub_rn(fi, floorf(fi));
    int ii = (int)floorf(__fmul_rn(fi, LUTN_F));
    ii = ii < 0 ? 0 : (ii > 4095 ? 4095 : ii);
    float ci = cosf(__fmul_rn((float)ii, ANG_STEP));

    int base = (b * SS + s) * D2;

    __nv_bfloat16 h, l;
    h = __float2bfloat16_rn(cr); l = __float2bfloat16_rn(cr - __bfloat162float(h));
    g_Qh[base + d] = h; g_Ql[base + d] = l;
    h = __float2bfloat16_rn(ci); l = __float2bfloat16_rn(ci - __bfloat162float(h));
    g_Qh[base + d + DD] = h; g_Ql[base + d + DD] = l;
    h = __float2bfloat16_rn(xr); l = __float2bfloat16_rn(xr - __bfloat162float(h));
    g_Kh[base + d] = h; g_Kl[base + d] = l;
    h = __float2bfloat16_rn(xi); l = __float2bfloat16_rn(xi - __bfloat162float(h));
    g_Kh[base + d + DD] = h; g_Kl[base + d + DD] = l;
}

// ============ Kernel 2: causal flash attention (mma.sync bf16 split, split-KV x2) ============
__global__ __launch_bounds__(256, 1) void attn_mma() {
    extern __shared__ char sm[];
    const uint32_t su = smem_u32(sm);
    const uint32_t sQh_u = su + OFF_QH, sQl_u = su + OFF_QL;
    const uint32_t sKh_u = su + OFF_KH, sKl_u = su + OFF_KL;

    const int tid  = threadIdx.x;
    const int wid  = tid >> 5;
    const int lane = tid & 31;
    const int lr = lane & 7, q4 = lane >> 3;
    const int g  = lane >> 2, t = lane & 3;

    const int bid = blockIdx.x;
    const int m   = 63 - (bid >> 2);      // longest tiles first
    const int b   = (bid >> 1) & 1;
    const int sid = bid & 1;
    const int q0  = m << 7;
    const int j0  = sid * (m + 1);
    const int j1  = j0 + (m + 1);

    const char* Qhg = (const char*)(g_Qh + b * (SS * D2) + q0 * D2);
    const char* Qlg = (const char*)(g_Ql + b * (SS * D2) + q0 * D2);
    const char* Khg = (const char*)(g_Kh + b * (SS * D2));
    const char* Klg = (const char*)(g_Kl + b * (SS * D2));

    // ---- load Q tiles (128 rows x 256B), swizzled ----
    for (int e = tid; e < 2048; e += 256) {
        int r = e >> 4, u = e & 15;
        int so = r * 256 + ((u ^ (r & 7)) << 4);
        int go = r * 256 + u * 16;
        *(uint4*)(sm + OFF_QH + so) = *(const uint4*)(Qhg + go);
        *(uint4*)(sm + OFF_QL + so) = *(const uint4*)(Qlg + go);
    }

    // A-frag (Q) lane addressing
    const int rowA = wid * 16 + lr + 8 * (q4 & 1);
    const int swA = rowA & 7;
    const int unitAx = q4 >> 1;
    const uint32_t aRow = (uint32_t)rowA * 256u;
    // B-frag (K rows as n) lane addressing
    const int rowBo = lr + 8 * (q4 >> 1);
    const int unitBx = q4 & 1;
    // V-frag (trans) lane addressing
    const int rowVo = lr + 8 * (q4 & 1);
    const int unitVx = q4 >> 1;

    float o[16][4];
    #pragma unroll
    for (int i = 0; i < 16; i++)
        #pragma unroll
        for (int c = 0; c < 4; c++) o[i][c] = 0.f;
    float l0 = 0.f, l1 = 0.f;

    const float SC = 0.0883883476483184405501f;  // 1/sqrt(128)
    const int row0 = q0 + wid * 16 + g;

    for (int j = j0; j < j1; ++j) {
        const int k0 = j << 6;
        if (j > j0) __syncthreads();
        // ---- load K tiles (64 rows x 256B), hi+lo ----
        for (int e = tid; e < 1024; e += 256) {
            int r = e >> 4, u = e & 15;
            int so = r * 256 + ((u ^ (r & 7)) << 4);
            int go = (k0 + r) * 256 + u * 16;
            *(uint4*)(sm + OFF_KH + so) = *(const uint4*)(Khg + go);
            *(uint4*)(sm + OFF_KL + so) = *(const uint4*)(Klg + go);
        }
        __syncthreads();

        // ---- QK: S[16x64] = Qh.Kh + Qh.Kl + Ql.Kh ----
        float s[8][4];
        #pragma unroll
        for (int i = 0; i < 8; i++)
            #pragma unroll
            for (int c = 0; c < 4; c++) s[i][c] = 0.f;

        #pragma unroll
        for (int kb = 0; kb < 8; kb++) {
            uint32_t aH[4], aL[4];
            uint32_t ao = aRow + (uint32_t)(((2 * kb + unitAx) ^ swA) << 4);
            ldsm4(aH, sQh_u + ao);
            ldsm4(aL, sQl_u + ao);
            #pragma unroll
            for (int nb2 = 0; nb2 < 4; nb2++) {
                int rB = nb2 * 16 + rowBo;
                uint32_t bo = (uint32_t)(rB * 256 + (((2 * kb + unitBx) ^ (rB & 7)) << 4));
                uint32_t bH[4], bL[4];
                ldsm4(bH, sKh_u + bo);
                ldsm4(bL, sKl_u + bo);
                mma16816(s[2 * nb2],     aH, &bH[0]);
                mma16816(s[2 * nb2],     aH, &bL[0]);
                mma16816(s[2 * nb2],     aL, &bH[0]);
                mma16816(s[2 * nb2 + 1], aH, &bH[2]);
                mma16816(s[2 * nb2 + 1], aH, &bL[2]);
                mma16816(s[2 * nb2 + 1], aL, &bH[2]);
            }
        }

        // ---- epilogue: mask + exp + build P frags in registers ----
        uint32_t ph0[8], ph1[8], pl0[8], pl1[8];
        const bool full = (k0 + 63 <= q0 + wid * 16);
        #pragma unroll
        for (int nb = 0; nb < 8; nb++) {
            float e0, e1, e2, e3;
            if (full) {
                e0 = __expf(s[nb][0] * SC);
                e1 = __expf(s[nb][1] * SC);
                e2 = __expf(s[nb][2] * SC);
                e3 = __expf(s[nb][3] * SC);
            } else {
                int col = k0 + nb * 8 + 2 * t;
                e0 = (col     <= row0    ) ? __expf(s[nb][0] * SC) : 0.f;
                e1 = (col + 1 <= row0    ) ? __expf(s[nb][1] * SC) : 0.f;
                e2 = (col     <= row0 + 8) ? __expf(s[nb][2] * SC) : 0.f;
                e3 = (col + 1 <= row0 + 8) ? __expf(s[nb][3] * SC) : 0.f;
            }
            l0 += e0 + e1;
            l1 += e2 + e3;
            split2(e0, e1, ph0[nb], pl0[nb]);
            split2(e2, e3, ph1[nb], pl1[nb]);
        }

        // ---- PV: O[16x128] += Ph.Vh + Ph.Vl + Pl.Vh  (V = K tile, trans frags) ----
        #pragma unroll
        for (int kb = 0; kb < 4; kb++) {
            uint32_t aPh[4] = { ph0[2 * kb], ph1[2 * kb], ph0[2 * kb + 1], ph1[2 * kb + 1] };
            uint32_t aPl[4] = { pl0[2 * kb], pl1[2 * kb], pl0[2 * kb + 1], pl1[2 * kb + 1] };
            #pragma unroll
            for (int db2 = 0; db2 < 8; db2++) {
                int rV = kb * 16 + rowVo;
                uint32_t vo = (uint32_t)(rV * 256 + (((2 * db2 + unitVx) ^ (rV & 7)) << 4));
                uint32_t bH[4], bL[4];
                ldsm4t(bH, sKh_u + vo);
                ldsm4t(bL, sKl_u + vo);
                mma16816(o[2 * db2],     aPh, &bH[0]);
                mma16816(o[2 * db2],     aPh, &bL[0]);
                mma16816(o[2 * db2],     aPl, &bH[0]);
                mma16816(o[2 * db2 + 1], aPh, &bH[2]);
                mma16816(o[2 * db2 + 1], aPh, &bL[2]);
                mma16816(o[2 * db2 + 1], aPl, &bH[2]);
            }
        }
    }

    // ---- row-sum reduce (across the 4 lanes sharing a row) ----
    l0 += __shfl_xor_sync(0xffffffffu, l0, 1);
    l0 += __shfl_xor_sync(0xffffffffu, l0, 2);
    l1 += __shfl_xor_sync(0xffffffffu, l1, 1);
    l1 += __shfl_xor_sync(0xffffffffu, l1, 2);

    // ---- write unnormalized O and lsums ----
    float* Og = &g_O[sid][b * (SS * D2)];
    #pragma unroll
    for (int dt = 0; dt < 16; dt++) {
        int c = dt * 8 + 2 * t;
        *(float2*)(Og + row0 * D2 + c)       = make_float2(o[dt][0], o[dt][1]);
        *(float2*)(Og + (row0 + 8) * D2 + c) = make_float2(o[dt][2], o[dt][3]);
    }
    if (t == 0) {
        g_Ls[sid][b * SS + row0]     = l0;
        g_Ls[sid][b * SS + row0 + 8] = l1;
    }
}

// -------------------- Kernel 3: combine splits + normalize + fold --------------------
__global__ void combine_kernel() {
    int idx = blockIdx.x * blockDim.x + threadIdx.x;   // over B*S*64
    if (idx >= BB * SS * DD) return;
    int d = idx & 63;
    int bs = idx >> 6;
    float L = g_Ls[0][bs] + g_Ls[1][bs];
    float num = g_O[0][bs * D2 + d]      + g_O[1][bs * D2 + d]
              + g_O[0][bs * D2 + d + DD] + g_O[1][bs * D2 + d + DD];
    g_Z[idx] = num / L;
}

// -------------------- Kernel 4: EMA scan --------------------
__global__ void ema_kernel(const float* __restrict__ alpha_p,
                           float* __restrict__ out) {
    const int tid = threadIdx.x;   // 0..127
    const int b = tid >> 6;
    const int d = tid & 63;
    const float alpha = alpha_p[0];
    const float a  = 1.0f / (1.0f + expf(-alpha));
    const float na = 1.0f - a;

    const float* __restrict__ Z = g_Z + b * (SS * DD);
    float* __restrict__ O = out + b * (SS * DD);
    float e = 0.f;
    #pragma unroll 8
    for (int t = 0; t < SS; ++t) {
        e = a * Z[t * DD + d] + na * e;
        O[t * DD + d] = e;
    }
}

// -------------------- launch --------------------
extern "C" void kernel_launch(void* const* d_in, const int* in_sizes, int n_in,
                              void* d_out, int out_size) {
    const float* sr    = (const float*)d_in[0];
    const float* si    = (const float*)d_in[1];
    const float* pos   = (const float*)d_in[2];
    const float* w_q   = (const float*)d_in[3];
    const float* b_q   = (const float*)d_in[4];
    const float* alpha = (const float*)d_in[5];
    float* out = (float*)d_out;

    (void)in_sizes; (void)n_in; (void)out_size;

    cudaFuncSetAttribute(attn_mma,
                         cudaFuncAttributeMaxDynamicSharedMemorySize, SM_BYTES);

    const int nprep = BB * SS * DD;
    prep_kernel<<<(nprep + 255) / 256, 256>>>(sr, si, pos, w_q, b_q);
    attn_mma<<<256, 256, SM_BYTES>>>();
    combine_kernel<<<(BB * SS * DD + 255) / 256, 256>>>();
    ema_kernel<<<1, 128>>>(alpha, out);
}

// round 7
// speedup vs baseline: 2.5583x; 1.1656x over previous
#include <cuda_runtime.h>
#include <cuda_bf16.h>
#include <math.h>
#include <stdint.h>

// Shapes (fixed by the benchmark)
#define BB 2
#define SS 8192
#define DD 64
#define D2 128           // 2*D

// Smem layout: 4 bf16 tiles, 256B rows, XOR-swizzled in 16B units
#define OFF_QH 0          // 128 x 128 bf16 = 32KB
#define OFF_QL 32768
#define OFF_KH 65536      // 64 x 128 bf16 = 16KB
#define OFF_KL 81920
#define SM_BYTES 98304

// EMA chunking
#define EMA_CHUNK 512
#define EMA_LB    768
#define EMA_NCHUNK (SS / EMA_CHUNK)   // 16

// Scratch (static device globals -- no allocation allowed)
__device__ __nv_bfloat16 g_Qh[BB * SS * D2];
__device__ __nv_bfloat16 g_Ql[BB * SS * D2];
__device__ __nv_bfloat16 g_Kh[BB * SS * D2];
__device__ __nv_bfloat16 g_Kl[BB * SS * D2];
__device__ float g_O[2][BB * SS * D2];   // unnormalized O per kv-split (16MB)
__device__ float g_Ls[2][BB * SS];       // row exp-sums per split

// ---------------- helpers ----------------
__device__ __forceinline__ uint32_t smem_u32(const void* p) {
    uint32_t a;
    asm("{ .reg .u64 t; cvta.to.shared.u64 t, %1; cvt.u32.u64 %0, t; }"
        : "=r"(a) : "l"(p));
    return a;
}
__device__ __forceinline__ void ldsm4(uint32_t* r, uint32_t addr) {
    asm volatile("ldmatrix.sync.aligned.m8n8.x4.shared.b16 {%0,%1,%2,%3}, [%4];"
        : "=r"(r[0]), "=r"(r[1]), "=r"(r[2]), "=r"(r[3]) : "r"(addr));
}
__device__ __forceinline__ void ldsm4t(uint32_t* r, uint32_t addr) {
    asm volatile("ldmatrix.sync.aligned.m8n8.x4.trans.shared.b16 {%0,%1,%2,%3}, [%4];"
        : "=r"(r[0]), "=r"(r[1]), "=r"(r[2]), "=r"(r[3]) : "r"(addr));
}
__device__ __forceinline__ void mma16816(float* c, const uint32_t* a, const uint32_t* b) {
    asm volatile(
        "mma.sync.aligned.m16n8k16.row.col.f32.bf16.bf16.f32 "
        "{%0,%1,%2,%3}, {%4,%5,%6,%7}, {%8,%9}, {%0,%1,%2,%3};"
        : "+f"(c[0]), "+f"(c[1]), "+f"(c[2]), "+f"(c[3])
        : "r"(a[0]), "r"(a[1]), "r"(a[2]), "r"(a[3]), "r"(b[0]), "r"(b[1]));
}
// pack (x -> lo, y -> hi) as bf16x2, plus residual pack
__device__ __forceinline__ void split2(float x, float y, uint32_t& h, uint32_t& l) {
    asm("cvt.rn.bf16x2.f32 %0, %1, %2;" : "=r"(h) : "f"(y), "f"(x));
    float hx = __uint_as_float(h << 16);
    float hy = __uint_as_float(h & 0xffff0000u);
    asm("cvt.rn.bf16x2.f32 %0, %1, %2;" : "=r"(l) : "f"(y - hy), "f"(x - hx));
}

// -------------------- Kernel 1: prep Q (LUT cos) and K, bf16 hi/lo --------------------
__global__ void prep_kernel(const float* __restrict__ sr,
                            const float* __restrict__ si,
                            const float* __restrict__ pos,
                            const float* __restrict__ w_q,
                            const float* __restrict__ b_q) {
    const float PHI_F     = (float)1.6180339887498948482;
    const float INV2PI    = (float)(1.0 / 6.283185307179586476925286766559);
    const float LUTN_F    = 4096.0f;
    const float ANG_STEP  = (float)(6.283185307179586476925286766559 / 4096.0);

    int idx = blockIdx.x * blockDim.x + threadIdx.x;   // over B*S*D
    if (idx >= BB * SS * DD) return;
    int d = idx & (DD - 1);
    int s = (idx >> 6) & (SS - 1);
    int b = idx >> 19;

    float wl   = 1.0f + fabsf(w_q[d]);
    float bq   = b_q[d];
    float tphi = __fmul_rn(pos[s], PHI_F);

    float xr = sr[idx];
    float xi = si[idx];

    float thr = __fadd_rn(__fadd_rn(__fdiv_rn(xr, wl), bq), tphi);
    float thi = __fadd_rn(__fadd_rn(__fdiv_rn(xi, wl), bq), tphi);

    float fr = __fmul_rn(thr, INV2PI);
    fr = __fsub_rn(fr, floorf(fr));
    int ir = (int)floorf(__fmul_rn(fr, LUTN_F));
    ir = ir < 0 ? 0 : (ir > 4095 ? 4095 : ir);
    float cr = cosf(__fmul_rn((float)ir, ANG_STEP));

    float fi = __fmul_rn(thi, INV2PI);
    fi = __fsub_rn(fi, floorf(fi));
    int ii = (int)floorf(__fmul_rn(fi, LUTN_F));
    ii = ii < 0 ? 0 : (ii > 4095 ? 4095 : ii);
    float ci = cosf(__fmul_rn((float)ii, ANG_STEP));

    int base = (b * SS + s) * D2;

    __nv_bfloat16 h, l;
    h = __float2bfloat16_rn(cr); l = __float2bfloat16_rn(cr - __bfloat162float(h));
    g_Qh[base + d] = h; g_Ql[base + d] = l;
    h = __float2bfloat16_rn(ci); l = __float2bfloat16_rn(ci - __bfloat162float(h));
    g_Qh[base + d + DD] = h; g_Ql[base + d + DD] = l;
    h = __float2bfloat16_rn(xr); l = __float2bfloat16_rn(xr - __bfloat162float(h));
    g_Kh[base + d] = h; g_Kl[base + d] = l;
    h = __float2bfloat16_rn(xi); l = __float2bfloat16_rn(xi - __bfloat162float(h));
    g_Kh[base + d + DD] = h; g_Kl[base + d + DD] = l;
}

// ============ Kernel 2: causal flash attention (mma.sync bf16 split, split-KV x2) ============
__global__ __launch_bounds__(256, 1) void attn_mma() {
    extern __shared__ char sm[];
    const uint32_t su = smem_u32(sm);
    const uint32_t sQh_u = su + OFF_QH, sQl_u = su + OFF_QL;
    const uint32_t sKh_u = su + OFF_KH, sKl_u = su + OFF_KL;

    const int tid  = threadIdx.x;
    const int wid  = tid >> 5;
    const int lane = tid & 31;
    const int lr = lane & 7, q4 = lane >> 3;
    const int g  = lane >> 2, t = lane & 3;

    const int bid = blockIdx.x;
    const int m   = 63 - (bid >> 2);      // longest tiles first
    const int b   = (bid >> 1) & 1;
    const int sid = bid & 1;
    const int q0  = m << 7;
    const int j0  = sid * (m + 1);
    const int j1  = j0 + (m + 1);

    const char* Qhg = (const char*)(g_Qh + b * (SS * D2) + q0 * D2);
    const char* Qlg = (const char*)(g_Ql + b * (SS * D2) + q0 * D2);
    const char* Khg = (const char*)(g_Kh + b * (SS * D2));
    const char* Klg = (const char*)(g_Kl + b * (SS * D2));

    // ---- load Q tiles (128 rows x 256B), swizzled ----
    for (int e = tid; e < 2048; e += 256) {
        int r = e >> 4, u = e & 15;
        int so = r * 256 + ((u ^ (r & 7)) << 4);
        int go = r * 256 + u * 16;
        *(uint4*)(sm + OFF_QH + so) = *(const uint4*)(Qhg + go);
        *(uint4*)(sm + OFF_QL + so) = *(const uint4*)(Qlg + go);
    }

    // A-frag (Q) lane addressing
    const int rowA = wid * 16 + lr + 8 * (q4 & 1);
    const int swA = rowA & 7;
    const int unitAx = q4 >> 1;
    const uint32_t aRow = (uint32_t)rowA * 256u;
    // B-frag (K rows as n) lane addressing
    const int rowBo = lr + 8 * (q4 >> 1);
    const int unitBx = q4 & 1;
    // V-frag (trans) lane addressing
    const int rowVo = lr + 8 * (q4 & 1);
    const int unitVx = q4 >> 1;

    float o[16][4];
    #pragma unroll
    for (int i = 0; i < 16; i++)
        #pragma unroll
        for (int c = 0; c < 4; c++) o[i][c] = 0.f;
    float l0 = 0.f, l1 = 0.f;

    const float SC = 0.0883883476483184405501f;  // 1/sqrt(128)
    const int row0 = q0 + wid * 16 + g;

    for (int j = j0; j < j1; ++j) {
        const int k0 = j << 6;
        if (j > j0) __syncthreads();
        // ---- load K tiles (64 rows x 256B), hi+lo ----
        for (int e = tid; e < 1024; e += 256) {
            int r = e >> 4, u = e & 15;
            int so = r * 256 + ((u ^ (r & 7)) << 4);
            int go = (k0 + r) * 256 + u * 16;
            *(uint4*)(sm + OFF_KH + so) = *(const uint4*)(Khg + go);
            *(uint4*)(sm + OFF_KL + so) = *(const uint4*)(Klg + go);
        }
        __syncthreads();

        // ---- QK: S[16x64] = Qh.Kh + Qh.Kl + Ql.Kh ----
        float s[8][4];
        #pragma unroll
        for (int i = 0; i < 8; i++)
            #pragma unroll
            for (int c = 0; c < 4; c++) s[i][c] = 0.f;

        #pragma unroll
        for (int kb = 0; kb < 8; kb++) {
            uint32_t aH[4], aL[4];
            uint32_t ao = aRow + (uint32_t)(((2 * kb + unitAx) ^ swA) << 4);
            ldsm4(aH, sQh_u + ao);
            ldsm4(aL, sQl_u + ao);
            #pragma unroll
            for (int nb2 = 0; nb2 < 4; nb2++) {
                int rB = nb2 * 16 + rowBo;
                uint32_t bo = (uint32_t)(rB * 256 + (((2 * kb + unitBx) ^ (rB & 7)) << 4));
                uint32_t bH[4], bL[4];
                ldsm4(bH, sKh_u + bo);
                ldsm4(bL, sKl_u + bo);
                mma16816(s[2 * nb2],     aH, &bH[0]);
                mma16816(s[2 * nb2],     aH, &bL[0]);
                mma16816(s[2 * nb2],     aL, &bH[0]);
                mma16816(s[2 * nb2 + 1], aH, &bH[2]);
                mma16816(s[2 * nb2 + 1], aH, &bL[2]);
                mma16816(s[2 * nb2 + 1], aL, &bH[2]);
            }
        }

        // ---- epilogue: mask + exp + build P frags in registers ----
        uint32_t ph0[8], ph1[8], pl0[8], pl1[8];
        const bool full = (k0 + 63 <= q0 + wid * 16);
        #pragma unroll
        for (int nb = 0; nb < 8; nb++) {
            float e0, e1, e2, e3;
            if (full) {
                e0 = __expf(s[nb][0] * SC);
                e1 = __expf(s[nb][1] * SC);
                e2 = __expf(s[nb][2] * SC);
                e3 = __expf(s[nb][3] * SC);
            } else {
                int col = k0 + nb * 8 + 2 * t;
                e0 = (col     <= row0    ) ? __expf(s[nb][0] * SC) : 0.f;
                e1 = (col + 1 <= row0    ) ? __expf(s[nb][1] * SC) : 0.f;
                e2 = (col     <= row0 + 8) ? __expf(s[nb][2] * SC) : 0.f;
                e3 = (col + 1 <= row0 + 8) ? __expf(s[nb][3] * SC) : 0.f;
            }
            l0 += e0 + e1;
            l1 += e2 + e3;
            split2(e0, e1, ph0[nb], pl0[nb]);
            split2(e2, e3, ph1[nb], pl1[nb]);
        }

        // ---- PV: O[16x128] += Ph.Vh + Ph.Vl + Pl.Vh  (V = K tile, trans frags) ----
        #pragma unroll
        for (int kb = 0; kb < 4; kb++) {
            uint32_t aPh[4] = { ph0[2 * kb], ph1[2 * kb], ph0[2 * kb + 1], ph1[2 * kb + 1] };
            uint32_t aPl[4] = { pl0[2 * kb], pl1[2 * kb], pl0[2 * kb + 1], pl1[2 * kb + 1] };
            #pragma unroll
            for (int db2 = 0; db2 < 8; db2++) {
                int rV = kb * 16 + rowVo;
                uint32_t vo = (uint32_t)(rV * 256 + (((2 * db2 + unitVx) ^ (rV & 7)) << 4));
                uint32_t bH[4], bL[4];
                ldsm4t(bH, sKh_u + vo);
                ldsm4t(bL, sKl_u + vo);
                mma16816(o[2 * db2],     aPh, &bH[0]);
                mma16816(o[2 * db2],     aPh, &bL[0]);
                mma16816(o[2 * db2],     aPl, &bH[0]);
                mma16816(o[2 * db2 + 1], aPh, &bH[2]);
                mma16816(o[2 * db2 + 1], aPh, &bL[2]);
                mma16816(o[2 * db2 + 1], aPl, &bH[2]);
            }
        }
    }

    // ---- row-sum reduce (across the 4 lanes sharing a row) ----
    l0 += __shfl_xor_sync(0xffffffffu, l0, 1);
    l0 += __shfl_xor_sync(0xffffffffu, l0, 2);
    l1 += __shfl_xor_sync(0xffffffffu, l1, 1);
    l1 += __shfl_xor_sync(0xffffffffu, l1, 2);

    // ---- write unnormalized O and lsums ----
    float* Og = &g_O[sid][b * (SS * D2)];
    #pragma unroll
    for (int dt = 0; dt < 16; dt++) {
        int c = dt * 8 + 2 * t;
        *(float2*)(Og + row0 * D2 + c)       = make_float2(o[dt][0], o[dt][1]);
        *(float2*)(Og + (row0 + 8) * D2 + c) = make_float2(o[dt][2], o[dt][3]);
    }
    if (t == 0) {
        g_Ls[sid][b * SS + row0]     = l0;
        g_Ls[sid][b * SS + row0 + 8] = l1;
    }
}

// ------ Kernel 3: fused combine + fold + chunked EMA (windowed recurrence) ------
// EMA decay (1-a)^k is numerically dead after ~30 steps (a ~= 0.52), so each
// chunk of EMA_CHUNK outputs restarts the recurrence EMA_LB steps earlier from
// e=0; truncation error (1-a)^EMA_LB is far below fp32 epsilon. Chunk 0 exact.
__global__ __launch_bounds__(64, 1) void ema_chunk_kernel(
        const float* __restrict__ alpha_p, float* __restrict__ out) {
    const int d     = threadIdx.x;          // 0..63
    const int b     = blockIdx.x >> 4;
    const int chunk = blockIdx.x & 15;

    const float alpha = alpha_p[0];
    const float a  = 1.0f / (1.0f + expf(-alpha));
    const float na = 1.0f - a;

    const int t0     = chunk * EMA_CHUNK;
    const int tstart = (t0 - EMA_LB) > 0 ? (t0 - EMA_LB) : 0;
    const int tend   = t0 + EMA_CHUNK;

    const float* O0 = &g_O[0][b * (SS * D2)];
    const float* O1 = &g_O[1][b * (SS * D2)];
    const float* L0 = &g_Ls[0][b * SS];
    const float* L1 = &g_Ls[1][b * SS];
    float* __restrict__ Ob = out + b * (SS * DD);

    float e = 0.f;
    for (int t = tstart; t < tend; ++t) {
        const int r = t * D2;
        float num = O0[r + d] + O1[r + d] + O0[r + d + DD] + O1[r + d + DD];
        float L   = L0[t] + L1[t];
        float z   = num / L;
        e = a * z + na * e;
        if (t >= t0) Ob[t * DD + d] = e;
    }
}

// -------------------- launch --------------------
extern "C" void kernel_launch(void* const* d_in, const int* in_sizes, int n_in,
                              void* d_out, int out_size) {
    const float* sr    = (const float*)d_in[0];
    const float* si    = (const float*)d_in[1];
    const float* pos   = (const float*)d_in[2];
    const float* w_q   = (const float*)d_in[3];
    const float* b_q   = (const float*)d_in[4];
    const float* alpha = (const float*)d_in[5];
    float* out = (float*)d_out;

    (void)in_sizes; (void)n_in; (void)out_size;

    cudaFuncSetAttribute(attn_mma,
                         cudaFuncAttributeMaxDynamicSharedMemorySize, SM_BYTES);

    const int nprep = BB * SS * DD;
    prep_kernel<<<(nprep + 255) / 256, 256>>>(sr, si, pos, w_q, b_q);
    attn_mma<<<256, 256, SM_BYTES>>>();
    ema_chunk_kernel<<<BB * EMA_NCHUNK, 64>>>(alpha, out);
}

// round 11
// speedup vs baseline: 5.0722x; 1.9826x over previous
#include <cuda_runtime.h>
#include <cuda_bf16.h>
#include <math.h>
#include <stdint.h>

// Shapes (fixed by the benchmark)
#define BB 2
#define SS 8192
#define DD 64
#define D2 128           // 2*D

// Smem layout: 4 bf16 tiles, 256B rows, XOR-swizzled in 16B units
#define OFF_QH 0          // 128 x 128 bf16 = 32KB
#define OFF_QL 32768
#define OFF_KH 65536      // 64 x 128 bf16 = 16KB
#define OFF_KL 81920
#define SM_BYTES 98304

// EMA chunking
#define EMA_CHUNK 128
#define EMA_NCHUNK (SS / EMA_CHUNK)   // 64

// Scratch (static device globals -- no allocation allowed)
__device__ __nv_bfloat16 g_Qh[BB * SS * D2];
__device__ __nv_bfloat16 g_Ql[BB * SS * D2];
__device__ __nv_bfloat16 g_Kh[BB * SS * D2];
__device__ __nv_bfloat16 g_Kl[BB * SS * D2];
__device__ float g_O[2][BB * SS * DD];   // unnormalized, FOLDED (d + d+64) per split
__device__ float g_Ls[2][BB * SS];       // row exp-sums per split

// ---------------- helpers ----------------
__device__ __forceinline__ uint32_t smem_u32(const void* p) {
    uint32_t a;
    asm("{ .reg .u64 t; cvta.to.shared.u64 t, %1; cvt.u32.u64 %0, t; }"
        : "=r"(a) : "l"(p));
    return a;
}
__device__ __forceinline__ void ldsm4(uint32_t* r, uint32_t addr) {
    asm volatile("ldmatrix.sync.aligned.m8n8.x4.shared.b16 {%0,%1,%2,%3}, [%4];"
        : "=r"(r[0]), "=r"(r[1]), "=r"(r[2]), "=r"(r[3]) : "r"(addr));
}
__device__ __forceinline__ void ldsm4t(uint32_t* r, uint32_t addr) {
    asm volatile("ldmatrix.sync.aligned.m8n8.x4.trans.shared.b16 {%0,%1,%2,%3}, [%4];"
        : "=r"(r[0]), "=r"(r[1]), "=r"(r[2]), "=r"(r[3]) : "r"(addr));
}
__device__ __forceinline__ void mma16816(float* c, const uint32_t* a, const uint32_t* b) {
    asm volatile(
        "mma.sync.aligned.m16n8k16.row.col.f32.bf16.bf16.f32 "
        "{%0,%1,%2,%3}, {%4,%5,%6,%7}, {%8,%9}, {%0,%1,%2,%3};"
        : "+f"(c[0]), "+f"(c[1]), "+f"(c[2]), "+f"(c[3])
        : "r"(a[0]), "r"(a[1]), "r"(a[2]), "r"(a[3]), "r"(b[0]), "r"(b[1]));
}
// pack (x -> lo, y -> hi) as bf16x2, plus residual pack
__device__ __forceinline__ void split2(float x, float y, uint32_t& h, uint32_t& l) {
    asm("cvt.rn.bf16x2.f32 %0, %1, %2;" : "=r"(h) : "f"(y), "f"(x));
    float hx = __uint_as_float(h << 16);
    float hy = __uint_as_float(h & 0xffff0000u);
    asm("cvt.rn.bf16x2.f32 %0, %1, %2;" : "=r"(l) : "f"(y - hy), "f"(x - hx));
}

// -------------------- Kernel 1: prep Q (LUT cos) and K, bf16 hi/lo --------------------
__global__ void prep_kernel(const float* __restrict__ sr,
                            const float* __restrict__ si,
                            const float* __restrict__ pos,
                            const float* __restrict__ w_q,
                            const float* __restrict__ b_q) {
    const float PHI_F     = (float)1.6180339887498948482;
    const float INV2PI    = (float)(1.0 / 6.283185307179586476925286766559);
    const float LUTN_F    = 4096.0f;
    const float ANG_STEP  = (float)(6.283185307179586476925286766559 / 4096.0);

    int idx = blockIdx.x * blockDim.x + threadIdx.x;   // over B*S*D
    if (idx >= BB * SS * DD) return;
    int d = idx & (DD - 1);
    int s = (idx >> 6) & (SS - 1);
    int b = idx >> 19;

    float wl   = 1.0f + fabsf(w_q[d]);
    float bq   = b_q[d];
    float tphi = __fmul_rn(pos[s], PHI_F);

    float xr = sr[idx];
    float xi = si[idx];

    float thr = __fadd_rn(__fadd_rn(__fdiv_rn(xr, wl), bq), tphi);
    float thi = __fadd_rn(__fadd_rn(__fdiv_rn(xi, wl), bq), tphi);

    float fr = __fmul_rn(thr, INV2PI);
    fr = __fsub_rn(fr, floorf(fr));
    int ir = (int)floorf(__fmul_rn(fr, LUTN_F));
    ir = ir < 0 ? 0 : (ir > 4095 ? 4095 : ir);
    float cr = cosf(__fmul_rn((float)ir, ANG_STEP));

    float fi = __fmul_rn(thi, INV2PI);
    fi = __fsub_rn(fi, floorf(fi));
    int ii = (int)floorf(__fmul_rn(fi, LUTN_F));
    ii = ii < 0 ? 0 : (ii > 4095 ? 4095 : ii);
    float ci = cosf(__fmul_rn((float)ii, ANG_STEP));

    int base = (b * SS + s) * D2;

    __nv_bfloat16 h, l;
    h = __float2bfloat16_rn(cr); l = __float2bfloat16_rn(cr - __bfloat162float(h));
    g_Qh[base + d] = h; g_Ql[base + d] = l;
    h = __float2bfloat16_rn(ci); l = __float2bfloat16_rn(ci - __bfloat162float(h));
    g_Qh[base + d + DD] = h; g_Ql[base + d + DD] = l;
    h = __float2bfloat16_rn(xr); l = __float2bfloat16_rn(xr - __bfloat162float(h));
    g_Kh[base + d] = h; g_Kl[base + d] = l;
    h = __float2bfloat16_rn(xi); l = __float2bfloat16_rn(xi - __bfloat162float(h));
    g_Kh[base + d + DD] = h; g_Kl[base + d + DD] = l;
}

// ============ Kernel 2: causal flash attention (mma.sync bf16 split, split-KV x2) ============
__global__ __launch_bounds__(256, 1) void attn_mma() {
    extern __shared__ char sm[];
    const uint32_t su = smem_u32(sm);
    const uint32_t sQh_u = su + OFF_QH, sQl_u = su + OFF_QL;
    const uint32_t sKh_u = su + OFF_KH, sKl_u = su + OFF_KL;

    const int tid  = threadIdx.x;
    const int wid  = tid >> 5;
    const int lane = tid & 31;
    const int lr = lane & 7, q4 = lane >> 3;
    const int g  = lane >> 2, t = lane & 3;

    const int bid = blockIdx.x;
    const int m   = 63 - (bid >> 2);      // longest tiles first
    const int b   = (bid >> 1) & 1;
    const int sid = bid & 1;
    const int q0  = m << 7;
    const int j0  = sid * (m + 1);
    const int j1  = j0 + (m + 1);

    const char* Qhg = (const char*)(g_Qh + b * (SS * D2) + q0 * D2);
    const char* Qlg = (const char*)(g_Ql + b * (SS * D2) + q0 * D2);
    const char* Khg = (const char*)(g_Kh + b * (SS * D2));
    const char* Klg = (const char*)(g_Kl + b * (SS * D2));

    // ---- load Q tiles (128 rows x 256B), swizzled ----
    for (int e = tid; e < 2048; e += 256) {
        int r = e >> 4, u = e & 15;
        int so = r * 256 + ((u ^ (r & 7)) << 4);
        int go = r * 256 + u * 16;
        *(uint4*)(sm + OFF_QH + so) = *(const uint4*)(Qhg + go);
        *(uint4*)(sm + OFF_QL + so) = *(const uint4*)(Qlg + go);
    }

    // A-frag (Q) lane addressing
    const int rowA = wid * 16 + lr + 8 * (q4 & 1);
    const int swA = rowA & 7;
    const int unitAx = q4 >> 1;
    const uint32_t aRow = (uint32_t)rowA * 256u;
    // B-frag (K rows as n) lane addressing
    const int rowBo = lr + 8 * (q4 >> 1);
    const int unitBx = q4 & 1;
    // V-frag (trans) lane addressing
    const int rowVo = lr + 8 * (q4 & 1);
    const int unitVx = q4 >> 1;

    float o[16][4];
    #pragma unroll
    for (int i = 0; i < 16; i++)
        #pragma unroll
        for (int c = 0; c < 4; c++) o[i][c] = 0.f;
    float l0 = 0.f, l1 = 0.f;

    const float SC = 0.0883883476483184405501f;  // 1/sqrt(128)
    const int row0 = q0 + wid * 16 + g;

    for (int j = j0; j < j1; ++j) {
        const int k0 = j << 6;
        if (j > j0) __syncthreads();
        // ---- load K tiles (64 rows x 256B), hi+lo ----
        for (int e = tid; e < 1024; e += 256) {
            int r = e >> 4, u = e & 15;
            int so = r * 256 + ((u ^ (r & 7)) << 4);
            int go = (k0 + r) * 256 + u * 16;
            *(uint4*)(sm + OFF_KH + so) = *(const uint4*)(Khg + go);
            *(uint4*)(sm + OFF_KL + so) = *(const uint4*)(Klg + go);
        }
        __syncthreads();

        // ---- QK: S[16x64] = Qh.Kh + Qh.Kl + Ql.Kh ----
        float s[8][4];
        #pragma unroll
        for (int i = 0; i < 8; i++)
            #pragma unroll
            for (int c = 0; c < 4; c++) s[i][c] = 0.f;

        #pragma unroll
        for (int kb = 0; kb < 8; kb++) {
            uint32_t aH[4], aL[4];
            uint32_t ao = aRow + (uint32_t)(((2 * kb + unitAx) ^ swA) << 4);
            ldsm4(aH, sQh_u + ao);
            ldsm4(aL, sQl_u + ao);
            #pragma unroll
            for (int nb2 = 0; nb2 < 4; nb2++) {
                int rB = nb2 * 16 + rowBo;
                uint32_t bo = (uint32_t)(rB * 256 + (((2 * kb + unitBx) ^ (rB & 7)) << 4));
                uint32_t bH[4], bL[4];
                ldsm4(bH, sKh_u + bo);
                ldsm4(bL, sKl_u + bo);
                mma16816(s[2 * nb2],     aH, &bH[0]);
                mma16816(s[2 * nb2],     aH, &bL[0]);
                mma16816(s[2 * nb2],     aL, &bH[0]);
                mma16816(s[2 * nb2 + 1], aH, &bH[2]);
                mma16816(s[2 * nb2 + 1], aH, &bL[2]);
                mma16816(s[2 * nb2 + 1], aL, &bH[2]);
            }
        }

        // ---- epilogue: mask + exp + build P frags in registers ----
        uint32_t ph0[8], ph1[8], pl0[8], pl1[8];
        const bool full = (k0 + 63 <= q0 + wid * 16);
        #pragma unroll
        for (int nb = 0; nb < 8; nb++) {
            float e0, e1, e2, e3;
            if (full) {
                e0 = __expf(s[nb][0] * SC);
                e1 = __expf(s[nb][1] * SC);
                e2 = __expf(s[nb][2] * SC);
                e3 = __expf(s[nb][3] * SC);
            } else {
                int col = k0 + nb * 8 + 2 * t;
                e0 = (col     <= row0    ) ? __expf(s[nb][0] * SC) : 0.f;
                e1 = (col + 1 <= row0    ) ? __expf(s[nb][1] * SC) : 0.f;
                e2 = (col     <= row0 + 8) ? __expf(s[nb][2] * SC) : 0.f;
                e3 = (col + 1 <= row0 + 8) ? __expf(s[nb][3] * SC) : 0.f;
            }
            l0 += e0 + e1;
            l1 += e2 + e3;
            split2(e0, e1, ph0[nb], pl0[nb]);
            split2(e2, e3, ph1[nb], pl1[nb]);
        }

        // ---- PV: O[16x128] += Ph.Vh + Ph.Vl + Pl.Vh  (V = K tile, trans frags) ----
        #pragma unroll
        for (int kb = 0; kb < 4; kb++) {
            uint32_t aPh[4] = { ph0[2 * kb], ph1[2 * kb], ph0[2 * kb + 1], ph1[2 * kb + 1] };
            uint32_t aPl[4] = { pl0[2 * kb], pl1[2 * kb], pl0[2 * kb + 1], pl1[2 * kb + 1] };
            #pragma unroll
            for (int db2 = 0; db2 < 8; db2++) {
                int rV = kb * 16 + rowVo;
                uint32_t vo = (uint32_t)(rV * 256 + (((2 * db2 + unitVx) ^ (rV & 7)) << 4));
                uint32_t bH[4], bL[4];
                ldsm4t(bH, sKh_u + vo);
                ldsm4t(bL, sKl_u + vo);
                mma16816(o[2 * db2],     aPh, &bH[0]);
                mma16816(o[2 * db2],     aPh, &bL[0]);
                mma16816(o[2 * db2],     aPl, &bH[0]);
                mma16816(o[2 * db2 + 1], aPh, &bH[2]);
                mma16816(o[2 * db2 + 1], aPh, &bL[2]);
                mma16816(o[2 * db2 + 1], aPl, &bH[2]);
            }
        }
    }

    // ---- row-sum reduce (across the 4 lanes sharing a row) ----
    l0 += __shfl_xor_sync(0xffffffffu, l0, 1);
    l0 += __shfl_xor_sync(0xffffffffu, l0, 2);
    l1 += __shfl_xor_sync(0xffffffffu, l1, 1);
    l1 += __shfl_xor_sync(0xffffffffu, l1, 2);

    // ---- fold (c and c+64) in registers, write unnormalized folded O + lsums ----
    float* Og = &g_O[sid][b * (SS * DD)];
    #pragma unroll
    for (int dt = 0; dt < 8; dt++) {
        int c = dt * 8 + 2 * t;   // 0..63
        float f0 = o[dt][0] + o[dt + 8][0];
        float f1 = o[dt][1] + o[dt + 8][1];
        float f2 = o[dt][2] + o[dt + 8][2];
        float f3 = o[dt][3] + o[dt + 8][3];
        *(float2*)(Og + row0 * DD + c)       = make_float2(f0, f1);
        *(float2*)(Og + (row0 + 8) * DD + c) = make_float2(f2, f3);
    }
    if (t == 0) {
        g_Ls[sid][b * SS + row0]     = l0;
        g_Ls[sid][b * SS + row0 + 8] = l1;
    }
}

// ------ Kernel 3: combine splits + chunked EMA (windowed, batch-prefetched) ------
// (1-a)^k decays below 2^-40 after lb steps; each chunk of EMA_CHUNK outputs
// restarts the recurrence lb steps earlier from e=0. Batch-of-8 loads give
// MLP ~16 so L2 latency is amortized instead of serialized.
__global__ __launch_bounds__(64, 1) void ema_chunk_kernel(
        const float* __restrict__ alpha_p, float* __restrict__ out) {
    const int d     = threadIdx.x;              // 0..63
    const int b     = blockIdx.x >> 6;
    const int chunk = blockIdx.x & 63;

    const float alpha = alpha_p[0];
    const float a  = 1.0f / (1.0f + expf(-alpha));
    const float na = 1.0f - a;

    // adaptive lookback: (1-a)^lb <= 2^-40, rounded to 8, clamped
    float dl = -log2f(na);
    int lb = (int)ceilf(40.0f / fmaxf(dl, 1e-6f));
    lb = (lb + 7) & ~7;
    lb = lb < 8 ? 8 : (lb > 2048 ? 2048 : lb);

    const int t0     = chunk * EMA_CHUNK;
    int tstart       = t0 - lb;
    if (tstart < 0) tstart = 0;
    const int tend   = t0 + EMA_CHUNK;

    const float* __restrict__ O0 = &g_O[0][b * (SS * DD)];
    const float* __restrict__ O1 = &g_O[1][b * (SS * DD)];
    const float* __restrict__ L0 = &g_Ls[0][b * SS];
    const float* __restrict__ L1 = &g_Ls[1][b * SS];
    float* __restrict__ Ob = out + b * (SS * DD);

    float e = 0.f;
    for (int t = tstart; t < tend; t += 8) {
        float z[8];
        #pragma unroll
        for (int i = 0; i < 8; i++) {
            const int tt = t + i;
            float num = O0[tt * DD + d] + O1[tt * DD + d];
            z[i] = num / (L0[tt] + L1[tt]);
        }
        #pragma unroll
        for (int i = 0; i < 8; i++) {
            e = a * z[i] + na * e;
            if (t + i >= t0) Ob[(t + i) * DD + d] = e;
        }
    }
}

// -------------------- launch --------------------
extern "C" void kernel_launch(void* const* d_in, const int* in_sizes, int n_in,
                              void* d_out, int out_size) {
    const float* sr    = (const float*)d_in[0];
    const float* si    = (const float*)d_in[1];
    const float* pos   = (const float*)d_in[2];
    const float* w_q   = (const float*)d_in[3];
    const float* b_q   = (const float*)d_in[4];
    const float* alpha = (const float*)d_in[5];
    float* out = (float*)d_out;

    (void)in_sizes; (void)n_in; (void)out_size;

    cudaFuncSetAttribute(attn_mma,
                         cudaFuncAttributeMaxDynamicSharedMemorySize, SM_BYTES);

    const int nprep = BB * SS * DD;
    prep_kernel<<<(nprep + 255) / 256, 256>>>(sr, si, pos, w_q, b_q);
    attn_mma<<<256, 256, SM_BYTES>>>();
    ema_chunk_kernel<<<BB * EMA_NCHUNK, 64>>>(alpha, out);
}